// round 1
// baseline (speedup 1.0000x reference)
#include <cuda_runtime.h>
#include <cstdint>

// Problem constants (from reference setup_inputs)
#define NDRUG 100000
#define NSIDE 5000
#define FDIM  128   // IN == HID

// ---------------------------------------------------------------------------
// Static device scratch (no cudaMalloc allowed)
// ---------------------------------------------------------------------------
__device__ __align__(16) float g_rs_r_src[NDRUG];   // rsqrt(deg of drug in relate_src)
__device__ __align__(16) float g_rs_r_dst[NSIDE];   // rsqrt(deg of side in relate_dst)
__device__ __align__(16) float g_rs_s_src[NDRUG];   // rsqrt(deg of drug in sim_src)
__device__ __align__(16) float g_rs_s_dst[NDRUG];   // rsqrt(deg of drug in sim_dst)

__device__ __align__(16) float g_hd_a[NDRUG * FDIM];
__device__ __align__(16) float g_hd_b[NDRUG * FDIM];
__device__ __align__(16) float g_hs_a[NSIDE * FDIM];
__device__ __align__(16) float g_hs_b[NSIDE * FDIM];

__device__ __align__(16) float g_y_rel[NDRUG * FDIM];
__device__ __align__(16) float g_y_relby[NSIDE * FDIM];
__device__ __align__(16) float g_y_sim[NDRUG * FDIM];
__device__ __align__(16) float g_y_simby[NDRUG * FDIM];

__device__ __align__(16) float g_agg_s[NSIDE * FDIM];
__device__ __align__(16) float g_agg_d1[NDRUG * FDIM];
__device__ __align__(16) float g_agg_d2[NDRUG * FDIM];
__device__ __align__(16) float g_agg_d3[NDRUG * FDIM];

// ---------------------------------------------------------------------------
// Small utility kernels
// ---------------------------------------------------------------------------
__global__ void zero_k(float4* __restrict__ p, int n4) {
    int i = blockIdx.x * blockDim.x + threadIdx.x;
    if (i < n4) p[i] = make_float4(0.f, 0.f, 0.f, 0.f);
}

__global__ void deg_kernel(const int* __restrict__ rsrc, const int* __restrict__ rdst,
                           const int* __restrict__ ssrc, const int* __restrict__ sdst,
                           int Er, int Es,
                           float* __restrict__ dr_src, float* __restrict__ dr_dst,
                           float* __restrict__ ds_src, float* __restrict__ ds_dst) {
    int i = blockIdx.x * blockDim.x + threadIdx.x;
    if (i < Er) {
        atomicAdd(&dr_src[rsrc[i]], 1.f);
        atomicAdd(&dr_dst[rdst[i]], 1.f);
    }
    if (i < Es) {
        atomicAdd(&ds_src[ssrc[i]], 1.f);
        atomicAdd(&ds_dst[sdst[i]], 1.f);
    }
}

__global__ void finish_deg(float* __restrict__ a,  // [NDRUG]
                           float* __restrict__ b,  // [NSIDE]
                           float* __restrict__ c,  // [NDRUG]
                           float* __restrict__ d)  // [NDRUG]
{
    int i = blockIdx.x * blockDim.x + threadIdx.x;
    if (i < NDRUG) {
        a[i] = rsqrtf(fmaxf(a[i], 1.f));
        c[i] = rsqrtf(fmaxf(c[i], 1.f));
        d[i] = rsqrtf(fmaxf(d[i], 1.f));
    }
    if (i < NSIDE) {
        b[i] = rsqrtf(fmaxf(b[i], 1.f));
    }
}

// ---------------------------------------------------------------------------
// Fused scale+GEMM: Y[n, NOUT] = (X[n,128] * rs[n]) @ W[128, NOUT]
// 64 rows per block, 256 threads, W + X tiles staged in dynamic shared memory.
// ---------------------------------------------------------------------------
template <int NOUT>
__global__ void gemm_scaled(const float* __restrict__ X, const float* __restrict__ rs,
                            const float* __restrict__ W, float* __restrict__ Y, int n) {
    extern __shared__ float smbuf[];
    float* Xs = smbuf;              // 64 * 128 floats
    float* Ws = smbuf + 64 * 128;   // 128 * NOUT floats

    const int tid = threadIdx.x;
    const int row0 = blockIdx.x * 64;

    // Load W tile (whole 128 x NOUT matrix for this relation)
    {
        const float4* W4 = reinterpret_cast<const float4*>(W);
        float4* Ws4 = reinterpret_cast<float4*>(Ws);
        #pragma unroll
        for (int i = tid; i < 128 * NOUT / 4; i += 256) Ws4[i] = W4[i];
    }
    // Load X tile, fusing per-row rsqrt(deg_out) scale
    {
        const float4* X4 = reinterpret_cast<const float4*>(X);
        float4* Xs4 = reinterpret_cast<float4*>(Xs);
        #pragma unroll
        for (int i = tid; i < 64 * 32; i += 256) {
            int r = i >> 5;
            int row = row0 + r;
            float4 v = make_float4(0.f, 0.f, 0.f, 0.f);
            if (row < n) {
                v = X4[row * 32 + (i & 31)];
                float s = rs[row];
                v.x *= s; v.y *= s; v.z *= s; v.w *= s;
            }
            Xs4[i] = v;
        }
    }
    __syncthreads();

    const int rg = tid >> 5;       // row group 0..7 (8 rows each)
    const int lane = tid & 31;     // column group
    constexpr int CPT = NOUT / 32; // cols per thread (4 or 2)

    float acc[8][CPT];
    #pragma unroll
    for (int i = 0; i < 8; ++i)
        #pragma unroll
        for (int j = 0; j < CPT; ++j) acc[i][j] = 0.f;

    const float4* Xs4 = reinterpret_cast<const float4*>(Xs);

    for (int k4 = 0; k4 < 32; ++k4) {
        float4 xk[8];
        #pragma unroll
        for (int i = 0; i < 8; ++i) xk[i] = Xs4[(rg * 8 + i) * 32 + k4];
        #pragma unroll
        for (int kk = 0; kk < 4; ++kk) {
            int k = k4 * 4 + kk;
            float wv[CPT];
            if constexpr (CPT == 4) {
                float4 w = reinterpret_cast<const float4*>(Ws)[k * 32 + lane];
                wv[0] = w.x; wv[1] = w.y; wv[2] = w.z; wv[3] = w.w;
            } else {
                float2 w = reinterpret_cast<const float2*>(Ws)[k * 32 + lane];
                wv[0] = w.x; wv[1] = w.y;
            }
            #pragma unroll
            for (int i = 0; i < 8; ++i) {
                float xv = (kk == 0) ? xk[i].x : (kk == 1) ? xk[i].y : (kk == 2) ? xk[i].z : xk[i].w;
                #pragma unroll
                for (int j = 0; j < CPT; ++j) acc[i][j] = fmaf(xv, wv[j], acc[i][j]);
            }
        }
    }

    #pragma unroll
    for (int i = 0; i < 8; ++i) {
        int row = row0 + rg * 8 + i;
        if (row < n) {
            if constexpr (CPT == 4) {
                reinterpret_cast<float4*>(Y)[row * (NOUT / 4) + lane] =
                    make_float4(acc[i][0], acc[i][1], acc[i][2], acc[i][3]);
            } else {
                reinterpret_cast<float2*>(Y)[row * (NOUT / 2) + lane] =
                    make_float2(acc[i][0], acc[i][1]);
            }
        }
    }
}

// ---------------------------------------------------------------------------
// Edge scatter: A[dst[e]] += Y[src[e]], F4 float4's per row.
// One thread = one float4 of one edge; vectorized red.global (no return).
// ---------------------------------------------------------------------------
template <int F4>
__global__ void scatter_add(const float* __restrict__ Y, const int* __restrict__ src,
                            const int* __restrict__ dst, float* __restrict__ A, int E) {
    int idx = blockIdx.x * blockDim.x + threadIdx.x;
    int e = idx / F4;
    int c = idx - e * F4;
    if (e >= E) return;
    int s = src[e];
    int d = dst[e];
    float4 v = reinterpret_cast<const float4*>(Y)[s * F4 + c];
    float4* p = reinterpret_cast<float4*>(A) + d * F4 + c;
    asm volatile("red.global.add.v4.f32 [%0], {%1,%2,%3,%4};"
                 :: "l"(p), "f"(v.x), "f"(v.y), "f"(v.z), "f"(v.w)
                 : "memory");
}

// ---------------------------------------------------------------------------
// Finalize: apply rsqrt(deg_in) scale + bias (+ sum of 3 convs for drug) + ReLU
// ---------------------------------------------------------------------------
template <int F>
__global__ void finalize_side_k(const float* __restrict__ agg, const float* __restrict__ rs,
                                const float* __restrict__ b, float* __restrict__ out,
                                int n, int relu) {
    constexpr int F4 = F / 4;
    int idx = blockIdx.x * blockDim.x + threadIdx.x;
    if (idx >= n * F4) return;
    int row = idx / F4;
    int c = idx - row * F4;
    float4 a = reinterpret_cast<const float4*>(agg)[idx];
    float4 bb = reinterpret_cast<const float4*>(b)[c];   // relation 0 bias row
    float s = rs[row];
    float4 v;
    v.x = fmaf(a.x, s, bb.x);
    v.y = fmaf(a.y, s, bb.y);
    v.z = fmaf(a.z, s, bb.z);
    v.w = fmaf(a.w, s, bb.w);
    if (relu) {
        v.x = fmaxf(v.x, 0.f); v.y = fmaxf(v.y, 0.f);
        v.z = fmaxf(v.z, 0.f); v.w = fmaxf(v.w, 0.f);
    }
    reinterpret_cast<float4*>(out)[idx] = v;
}

template <int F>
__global__ void finalize_drug_k(const float* __restrict__ a1, const float* __restrict__ a2,
                                const float* __restrict__ a3,
                                const float* __restrict__ rs1, const float* __restrict__ rs2,
                                const float* __restrict__ rs3,
                                const float* __restrict__ b, float* __restrict__ out,
                                int n, int relu) {
    constexpr int F4 = F / 4;
    int idx = blockIdx.x * blockDim.x + threadIdx.x;
    if (idx >= n * F4) return;
    int row = idx / F4;
    int c = idx - row * F4;
    float4 v1 = reinterpret_cast<const float4*>(a1)[idx];
    float4 v2 = reinterpret_cast<const float4*>(a2)[idx];
    float4 v3 = reinterpret_cast<const float4*>(a3)[idx];
    float4 b1v = reinterpret_cast<const float4*>(b)[1 * F4 + c];
    float4 b2v = reinterpret_cast<const float4*>(b)[2 * F4 + c];
    float4 b3v = reinterpret_cast<const float4*>(b)[3 * F4 + c];
    float s1 = rs1[row], s2 = rs2[row], s3 = rs3[row];
    float4 v;
    v.x = fmaf(v1.x, s1, b1v.x) + fmaf(v2.x, s2, b2v.x) + fmaf(v3.x, s3, b3v.x);
    v.y = fmaf(v1.y, s1, b1v.y) + fmaf(v2.y, s2, b2v.y) + fmaf(v3.y, s3, b3v.y);
    v.z = fmaf(v1.z, s1, b1v.z) + fmaf(v2.z, s2, b2v.z) + fmaf(v3.z, s3, b3v.z);
    v.w = fmaf(v1.w, s1, b1v.w) + fmaf(v2.w, s2, b2v.w) + fmaf(v3.w, s3, b3v.w);
    if (relu) {
        v.x = fmaxf(v.x, 0.f); v.y = fmaxf(v.y, 0.f);
        v.z = fmaxf(v.z, 0.f); v.w = fmaxf(v.w, 0.f);
    }
    reinterpret_cast<float4*>(out)[idx] = v;
}

// ---------------------------------------------------------------------------
// Host side
// ---------------------------------------------------------------------------
struct Scratch {
    float *rs_r_src, *rs_r_dst, *rs_s_src, *rs_s_dst;
    float *hd_a, *hd_b, *hs_a, *hs_b;
    float *y_rel, *y_relby, *y_sim, *y_simby;
    float *agg_s, *agg_d1, *agg_d2, *agg_d3;
};

static inline int cdiv(long long a, long long b) { return (int)((a + b - 1) / b); }

template <int NOUT>
static void run_layer(const Scratch& S,
                      const float* hd_in, const float* hs_in,
                      float* hd_out, float* hs_out,
                      const float* W, const float* b,
                      const int* rsrc, const int* rdst, int Er,
                      const int* ssrc, const int* sdst, int Es,
                      int relu) {
    constexpr int F4 = NOUT / 4;
    const int smem = (64 * 128 + 128 * NOUT) * 4;
    const long long wstride = 128LL * NOUT;

    // Projections (fused rsqrt(deg_out) scale)
    gemm_scaled<NOUT><<<cdiv(NDRUG, 64), 256, smem>>>(hd_in, S.rs_r_src, W + 0 * wstride, S.y_rel, NDRUG);
    gemm_scaled<NOUT><<<cdiv(NSIDE, 64), 256, smem>>>(hs_in, S.rs_r_dst, W + 1 * wstride, S.y_relby, NSIDE);
    gemm_scaled<NOUT><<<cdiv(NDRUG, 64), 256, smem>>>(hd_in, S.rs_s_src, W + 2 * wstride, S.y_sim, NDRUG);
    gemm_scaled<NOUT><<<cdiv(NDRUG, 64), 256, smem>>>(hd_in, S.rs_s_dst, W + 3 * wstride, S.y_simby, NDRUG);

    // Zero accumulators
    zero_k<<<cdiv((long long)NSIDE * F4, 256), 256>>>((float4*)S.agg_s, NSIDE * F4);
    zero_k<<<cdiv((long long)NDRUG * F4, 256), 256>>>((float4*)S.agg_d1, NDRUG * F4);
    zero_k<<<cdiv((long long)NDRUG * F4, 256), 256>>>((float4*)S.agg_d2, NDRUG * F4);
    zero_k<<<cdiv((long long)NDRUG * F4, 256), 256>>>((float4*)S.agg_d3, NDRUG * F4);

    // Edge scatters
    scatter_add<F4><<<cdiv((long long)Er * F4, 256), 256>>>(S.y_rel, rsrc, rdst, S.agg_s, Er);
    scatter_add<F4><<<cdiv((long long)Er * F4, 256), 256>>>(S.y_relby, rdst, rsrc, S.agg_d1, Er);
    scatter_add<F4><<<cdiv((long long)Es * F4, 256), 256>>>(S.y_sim, ssrc, sdst, S.agg_d2, Es);
    scatter_add<F4><<<cdiv((long long)Es * F4, 256), 256>>>(S.y_simby, sdst, ssrc, S.agg_d3, Es);

    // Finalize (rsqrt(deg_in) scale + bias + sum + relu)
    finalize_side_k<NOUT><<<cdiv((long long)NSIDE * F4, 256), 256>>>(S.agg_s, S.rs_r_dst, b, hs_out, NSIDE, relu);
    finalize_drug_k<NOUT><<<cdiv((long long)NDRUG * F4, 256), 256>>>(
        S.agg_d1, S.agg_d2, S.agg_d3,
        S.rs_r_src, S.rs_s_dst, S.rs_s_src,
        b, hd_out, NDRUG, relu);
}

extern "C" void kernel_launch(void* const* d_in, const int* in_sizes, int n_in,
                              void* d_out, int out_size) {
    const float* embed_drug = (const float*)d_in[0];
    const float* embed_side = (const float*)d_in[1];
    const int* rsrc = (const int*)d_in[2];
    const int* rdst = (const int*)d_in[3];
    const int* ssrc = (const int*)d_in[4];
    const int* sdst = (const int*)d_in[5];
    const float* W1 = (const float*)d_in[6];
    const float* b1 = (const float*)d_in[7];
    const float* W2 = (const float*)d_in[8];
    const float* b2 = (const float*)d_in[9];
    const float* W3 = (const float*)d_in[10];
    const float* b3 = (const float*)d_in[11];
    const int Er = in_sizes[2];
    const int Es = in_sizes[4];

    cudaFuncSetAttribute(gemm_scaled<128>, cudaFuncAttributeMaxDynamicSharedMemorySize,
                         (64 * 128 + 128 * 128) * 4);
    cudaFuncSetAttribute(gemm_scaled<64>, cudaFuncAttributeMaxDynamicSharedMemorySize,
                         (64 * 128 + 128 * 64) * 4);

    Scratch S;
    cudaGetSymbolAddress((void**)&S.rs_r_src, g_rs_r_src);
    cudaGetSymbolAddress((void**)&S.rs_r_dst, g_rs_r_dst);
    cudaGetSymbolAddress((void**)&S.rs_s_src, g_rs_s_src);
    cudaGetSymbolAddress((void**)&S.rs_s_dst, g_rs_s_dst);
    cudaGetSymbolAddress((void**)&S.hd_a, g_hd_a);
    cudaGetSymbolAddress((void**)&S.hd_b, g_hd_b);
    cudaGetSymbolAddress((void**)&S.hs_a, g_hs_a);
    cudaGetSymbolAddress((void**)&S.hs_b, g_hs_b);
    cudaGetSymbolAddress((void**)&S.y_rel, g_y_rel);
    cudaGetSymbolAddress((void**)&S.y_relby, g_y_relby);
    cudaGetSymbolAddress((void**)&S.y_sim, g_y_sim);
    cudaGetSymbolAddress((void**)&S.y_simby, g_y_simby);
    cudaGetSymbolAddress((void**)&S.agg_s, g_agg_s);
    cudaGetSymbolAddress((void**)&S.agg_d1, g_agg_d1);
    cudaGetSymbolAddress((void**)&S.agg_d2, g_agg_d2);
    cudaGetSymbolAddress((void**)&S.agg_d3, g_agg_d3);

    // --- degrees (once; shared by all 3 layers) ---
    zero_k<<<cdiv(NDRUG / 4, 256), 256>>>((float4*)S.rs_r_src, NDRUG / 4);
    zero_k<<<cdiv(NSIDE / 4, 256), 256>>>((float4*)S.rs_r_dst, NSIDE / 4);
    zero_k<<<cdiv(NDRUG / 4, 256), 256>>>((float4*)S.rs_s_src, NDRUG / 4);
    zero_k<<<cdiv(NDRUG / 4, 256), 256>>>((float4*)S.rs_s_dst, NDRUG / 4);
    int Emax = Er > Es ? Er : Es;
    deg_kernel<<<cdiv(Emax, 256), 256>>>(rsrc, rdst, ssrc, sdst, Er, Es,
                                         S.rs_r_src, S.rs_r_dst, S.rs_s_src, S.rs_s_dst);
    finish_deg<<<cdiv(NDRUG, 256), 256>>>(S.rs_r_src, S.rs_r_dst, S.rs_s_src, S.rs_s_dst);

    // --- 3 layers ---
    run_layer<128>(S, embed_drug, embed_side, S.hd_a, S.hs_a, W1, b1,
                   rsrc, rdst, Er, ssrc, sdst, Es, 1);
    run_layer<128>(S, S.hd_a, S.hs_a, S.hd_b, S.hs_b, W2, b2,
                   rsrc, rdst, Er, ssrc, sdst, Es, 1);

    float* out = (float*)d_out;
    run_layer<64>(S, S.hd_b, S.hs_b, out /*hd: ND*64*/, out + (long long)NDRUG * 64 /*hs*/,
                  W3, b3, rsrc, rdst, Er, ssrc, sdst, Es, 0);
}

// round 2
// speedup vs baseline: 1.2996x; 1.2996x over previous
#include <cuda_runtime.h>
#include <cstdint>

#define NDRUG 100000
#define NSIDE 5000
#define FDIM  128
#define EMAX  1000000

typedef unsigned long long u64;

// ---------------------------------------------------------------------------
// Static device scratch
// ---------------------------------------------------------------------------
__device__ __align__(16) float g_rs_r_src[NDRUG];
__device__ __align__(16) float g_rs_r_dst[NSIDE];
__device__ __align__(16) float g_rs_s_src[NDRUG];
__device__ __align__(16) float g_rs_s_dst[NDRUG];

__device__ __align__(16) float g_hd_a[NDRUG * FDIM];
__device__ __align__(16) float g_hd_b[NDRUG * FDIM];
__device__ __align__(16) float g_hs_a[NSIDE * FDIM];
__device__ __align__(16) float g_hs_b[NSIDE * FDIM];

__device__ __align__(16) float g_y_rel[NDRUG * FDIM];
__device__ __align__(16) float g_y_relby[NSIDE * FDIM];
__device__ __align__(16) float g_y_sim[NDRUG * FDIM];
__device__ __align__(16) float g_y_simby[NDRUG * FDIM];

// CSR structures:
// A: grouped by relate_dst (side),  neighbors = relate_src (drug)
// B: grouped by relate_src (drug),  neighbors = relate_dst (side)
// C: grouped by sim_dst (drug),     neighbors = sim_src (drug)
// D: grouped by sim_src (drug),     neighbors = sim_dst (drug)
__device__ __align__(16) int g_cntA[NSIDE], g_offA[NSIDE], g_curA[NSIDE];
__device__ __align__(16) int g_cntB[NDRUG], g_offB[NDRUG], g_curB[NDRUG];
__device__ __align__(16) int g_cntC[NDRUG], g_offC[NDRUG], g_curC[NDRUG];
__device__ __align__(16) int g_cntD[NDRUG], g_offD[NDRUG], g_curD[NDRUG];
__device__ __align__(16) int g_idxA[EMAX], g_idxB[EMAX], g_idxC[EMAX], g_idxD[EMAX];
__device__ __align__(16) int g_bsum[1024];

// ---------------------------------------------------------------------------
// f32x2 packed helpers
// ---------------------------------------------------------------------------
__device__ __forceinline__ u64 pack2(float a, float b) {
    u64 r; asm("mov.b64 %0, {%1,%2};" : "=l"(r) : "f"(a), "f"(b)); return r;
}
__device__ __forceinline__ void unpack2(u64 v, float& a, float& b) {
    asm("mov.b64 {%0,%1}, %2;" : "=f"(a), "=f"(b) : "l"(v));
}
__device__ __forceinline__ void fma2(u64& acc, u64 x, u64 w) {
    asm("fma.rn.f32x2 %0, %1, %2, %0;" : "+l"(acc) : "l"(x), "l"(w));
}
__device__ __forceinline__ float fcomp(const float4& v, int kk) {
    return kk == 0 ? v.x : kk == 1 ? v.y : kk == 2 ? v.z : v.w;
}

// ---------------------------------------------------------------------------
// Utility kernels
// ---------------------------------------------------------------------------
__global__ void zero_i4(int4* __restrict__ p, int n4) {
    int i = blockIdx.x * blockDim.x + threadIdx.x;
    if (i < n4) p[i] = make_int4(0, 0, 0, 0);
}

__global__ void hist_kernel(const int* __restrict__ rsrc, const int* __restrict__ rdst,
                            const int* __restrict__ ssrc, const int* __restrict__ sdst,
                            int Er, int Es,
                            int* __restrict__ cA, int* __restrict__ cB,
                            int* __restrict__ cC, int* __restrict__ cD) {
    int e = blockIdx.x * blockDim.x + threadIdx.x;
    if (e < Er) {
        atomicAdd(&cA[rdst[e]], 1);
        atomicAdd(&cB[rsrc[e]], 1);
    }
    if (e < Es) {
        atomicAdd(&cC[sdst[e]], 1);
        atomicAdd(&cD[ssrc[e]], 1);
    }
}

__global__ void rs_all(const int* __restrict__ cA, const int* __restrict__ cB,
                       const int* __restrict__ cC, const int* __restrict__ cD,
                       float* __restrict__ rA, float* __restrict__ rB,
                       float* __restrict__ rC, float* __restrict__ rD) {
    int i = blockIdx.x * blockDim.x + threadIdx.x;
    if (i < NSIDE) rA[i] = rsqrtf((float)max(cA[i], 1));
    if (i < NDRUG) {
        rB[i] = rsqrtf((float)max(cB[i], 1));
        rC[i] = rsqrtf((float)max(cC[i], 1));
        rD[i] = rsqrtf((float)max(cD[i], 1));
    }
}

// ---- 2-level exclusive scan (n <= 1024*1024, nb <= 128) ----
__global__ void scan_blk(const int* __restrict__ in, int* __restrict__ out,
                         int* __restrict__ bsum, int n) {
    __shared__ int sm[1024];
    int t = threadIdx.x, i = blockIdx.x * 1024 + t;
    int v = (i < n) ? in[i] : 0;
    sm[t] = v; __syncthreads();
    for (int d = 1; d < 1024; d <<= 1) {
        int x = (t >= d) ? sm[t - d] : 0;
        __syncthreads();
        sm[t] += x;
        __syncthreads();
    }
    if (i < n) out[i] = sm[t] - v;
    if (t == 1023) bsum[blockIdx.x] = sm[1023];
}
__global__ void scan_top(int* __restrict__ bsum, int nb) {
    __shared__ int sm[128];
    int t = threadIdx.x;
    int v = (t < nb) ? bsum[t] : 0;
    sm[t] = v; __syncthreads();
    for (int d = 1; d < 128; d <<= 1) {
        int x = (t >= d) ? sm[t - d] : 0;
        __syncthreads();
        sm[t] += x;
        __syncthreads();
    }
    if (t < nb) bsum[t] = sm[t] - v;
}
__global__ void scan_add(int* __restrict__ out, const int* __restrict__ bsum, int n) {
    int i = blockIdx.x * 1024 + threadIdx.x;
    if (i < n) out[i] += bsum[blockIdx.x];
}
__global__ void copy_i(int* __restrict__ dst, const int* __restrict__ src, int n) {
    int i = blockIdx.x * blockDim.x + threadIdx.x;
    if (i < n) dst[i] = src[i];
}

__global__ void fill_all(const int* __restrict__ rsrc, const int* __restrict__ rdst,
                         const int* __restrict__ ssrc, const int* __restrict__ sdst,
                         int Er, int Es,
                         int* __restrict__ curA, int* __restrict__ idxA,
                         int* __restrict__ curB, int* __restrict__ idxB,
                         int* __restrict__ curC, int* __restrict__ idxC,
                         int* __restrict__ curD, int* __restrict__ idxD) {
    int e = blockIdx.x * blockDim.x + threadIdx.x;
    if (e < Er) {
        int s = rsrc[e], d = rdst[e];
        idxA[atomicAdd(&curA[d], 1)] = s;
        idxB[atomicAdd(&curB[s], 1)] = d;
    }
    if (e < Es) {
        int s = ssrc[e], d = sdst[e];
        idxC[atomicAdd(&curC[d], 1)] = s;
        idxD[atomicAdd(&curD[s], 1)] = d;
    }
}

// ---------------------------------------------------------------------------
// GEMM: Y[n, NOUT] = (X[n,128] * rs[n]) @ W[128, NOUT]   via fma.rn.f32x2
// 64 rows/block, 256 threads. Thread = 8 rows (4 packed pairs) x CPT cols.
// ---------------------------------------------------------------------------
template <int NOUT>
__global__ __launch_bounds__(256) void gemm_scaled(
    const float* __restrict__ X, const float* __restrict__ rs,
    const float* __restrict__ W, float* __restrict__ Y, int n) {
    extern __shared__ float smbuf[];
    float* Xs = smbuf;              // 64 * 128
    float* Ws = smbuf + 64 * 128;   // 128 * NOUT

    const int tid = threadIdx.x;
    const int row0 = blockIdx.x * 64;

    {
        const float4* W4 = reinterpret_cast<const float4*>(W);
        float4* Ws4 = reinterpret_cast<float4*>(Ws);
        for (int i = tid; i < 128 * NOUT / 4; i += 256) Ws4[i] = W4[i];
    }
    {
        const float4* X4 = reinterpret_cast<const float4*>(X);
        float4* Xs4 = reinterpret_cast<float4*>(Xs);
        for (int i = tid; i < 64 * 32; i += 256) {
            int r = i >> 5, row = row0 + r;
            float4 v = make_float4(0.f, 0.f, 0.f, 0.f);
            if (row < n) {
                v = X4[row * 32 + (i & 31)];
                float s = rs[row];
                v.x *= s; v.y *= s; v.z *= s; v.w *= s;
            }
            Xs4[i] = v;
        }
    }
    __syncthreads();

    const int rg = tid >> 5;
    const int lane = tid & 31;
    constexpr int CPT = NOUT / 32;   // 4 or 2

    u64 acc[4][CPT];
    #pragma unroll
    for (int p = 0; p < 4; ++p)
        #pragma unroll
        for (int j = 0; j < CPT; ++j) acc[p][j] = 0ull;

    const float4* Xs4 = reinterpret_cast<const float4*>(Xs);

    for (int k4 = 0; k4 < 32; ++k4) {
        float4 xk[8];
        #pragma unroll
        for (int i = 0; i < 8; ++i) xk[i] = Xs4[(rg * 8 + i) * 32 + k4];
        #pragma unroll
        for (int kk = 0; kk < 4; ++kk) {
            int k = k4 * 4 + kk;
            u64 ww[CPT];
            if constexpr (CPT == 4) {
                float4 w = reinterpret_cast<const float4*>(Ws)[k * 32 + lane];
                ww[0] = pack2(w.x, w.x); ww[1] = pack2(w.y, w.y);
                ww[2] = pack2(w.z, w.z); ww[3] = pack2(w.w, w.w);
            } else {
                float2 w = reinterpret_cast<const float2*>(Ws)[k * 32 + lane];
                ww[0] = pack2(w.x, w.x); ww[1] = pack2(w.y, w.y);
            }
            #pragma unroll
            for (int p = 0; p < 4; ++p) {
                u64 xp = pack2(fcomp(xk[2 * p], kk), fcomp(xk[2 * p + 1], kk));
                #pragma unroll
                for (int j = 0; j < CPT; ++j) fma2(acc[p][j], xp, ww[j]);
            }
        }
    }

    #pragma unroll
    for (int p = 0; p < 4; ++p) {
        int ra = row0 + rg * 8 + 2 * p;
        int rb = ra + 1;
        float lo[CPT], hi[CPT];
        #pragma unroll
        for (int j = 0; j < CPT; ++j) unpack2(acc[p][j], lo[j], hi[j]);
        if constexpr (CPT == 4) {
            if (ra < n)
                reinterpret_cast<float4*>(Y)[ra * 32 + lane] = make_float4(lo[0], lo[1], lo[2], lo[3]);
            if (rb < n)
                reinterpret_cast<float4*>(Y)[rb * 32 + lane] = make_float4(hi[0], hi[1], hi[2], hi[3]);
        } else {
            if (ra < n)
                reinterpret_cast<float2*>(Y)[ra * 32 + lane] = make_float2(lo[0], lo[1]);
            if (rb < n)
                reinterpret_cast<float2*>(Y)[rb * 32 + lane] = make_float2(hi[0], hi[1]);
        }
    }
}

// ---------------------------------------------------------------------------
// CSR gather (one warp per destination row)
// ---------------------------------------------------------------------------
__device__ __forceinline__ float4 segsum4(const float4* __restrict__ Y, int beg, int m,
                                          const int* __restrict__ idx, int lane) {
    float4 acc = make_float4(0.f, 0.f, 0.f, 0.f);
    for (int e0 = 0; e0 < m; e0 += 32) {
        int myi = (e0 + lane < m) ? idx[beg + e0 + lane] : 0;
        int lim = min(32, m - e0);
        #pragma unroll 4
        for (int j = 0; j < lim; ++j) {
            int s = __shfl_sync(0xffffffffu, myi, j);
            float4 v = Y[s * 32 + lane];
            acc.x += v.x; acc.y += v.y; acc.z += v.z; acc.w += v.w;
        }
    }
    return acc;
}
__device__ __forceinline__ float2 segsum2(const float2* __restrict__ Y, int beg, int m,
                                          const int* __restrict__ idx, int lane) {
    float2 acc = make_float2(0.f, 0.f);
    for (int e0 = 0; e0 < m; e0 += 32) {
        int myi = (e0 + lane < m) ? idx[beg + e0 + lane] : 0;
        int lim = min(32, m - e0);
        #pragma unroll 4
        for (int j = 0; j < lim; ++j) {
            int s = __shfl_sync(0xffffffffu, myi, j);
            float2 v = Y[s * 32 + lane];
            acc.x += v.x; acc.y += v.y;
        }
    }
    return acc;
}

template <int NOUT>
__global__ __launch_bounds__(256) void gather_side(
    const float* __restrict__ Y, const int* __restrict__ off, const int* __restrict__ cnt,
    const int* __restrict__ idx, const float* __restrict__ rs_in,
    const float* __restrict__ b, float* __restrict__ out, int relu) {
    int w = (blockIdx.x * blockDim.x + threadIdx.x) >> 5;
    int lane = threadIdx.x & 31;
    if (w >= NSIDE) return;
    int beg = off[w], m = cnt[w];
    float s = rs_in[w];
    if constexpr (NOUT == 128) {
        float4 a = segsum4(reinterpret_cast<const float4*>(Y), beg, m, idx, lane);
        float4 bb = reinterpret_cast<const float4*>(b)[lane];
        float4 v = make_float4(fmaf(a.x, s, bb.x), fmaf(a.y, s, bb.y),
                               fmaf(a.z, s, bb.z), fmaf(a.w, s, bb.w));
        if (relu) { v.x = fmaxf(v.x, 0.f); v.y = fmaxf(v.y, 0.f); v.z = fmaxf(v.z, 0.f); v.w = fmaxf(v.w, 0.f); }
        reinterpret_cast<float4*>(out)[w * 32 + lane] = v;
    } else {
        float2 a = segsum2(reinterpret_cast<const float2*>(Y), beg, m, idx, lane);
        float2 bb = reinterpret_cast<const float2*>(b)[lane];
        float2 v = make_float2(fmaf(a.x, s, bb.x), fmaf(a.y, s, bb.y));
        if (relu) { v.x = fmaxf(v.x, 0.f); v.y = fmaxf(v.y, 0.f); }
        reinterpret_cast<float2*>(out)[w * 32 + lane] = v;
    }
}

template <int NOUT>
__global__ __launch_bounds__(256) void gather_drug(
    const float* __restrict__ yB, const int* __restrict__ offB, const int* __restrict__ cntB,
    const int* __restrict__ idxB, const float* __restrict__ rsB,
    const float* __restrict__ yC, const int* __restrict__ offC, const int* __restrict__ cntC,
    const int* __restrict__ idxC, const float* __restrict__ rsC,
    const float* __restrict__ yD, const int* __restrict__ offD, const int* __restrict__ cntD,
    const int* __restrict__ idxD, const float* __restrict__ rsD,
    const float* __restrict__ b, float* __restrict__ out, int relu) {
    int w = (blockIdx.x * blockDim.x + threadIdx.x) >> 5;
    int lane = threadIdx.x & 31;
    if (w >= NDRUG) return;
    float s1 = rsB[w], s2 = rsC[w], s3 = rsD[w];
    if constexpr (NOUT == 128) {
        float4 a1 = segsum4(reinterpret_cast<const float4*>(yB), offB[w], cntB[w], idxB, lane);
        float4 a2 = segsum4(reinterpret_cast<const float4*>(yC), offC[w], cntC[w], idxC, lane);
        float4 a3 = segsum4(reinterpret_cast<const float4*>(yD), offD[w], cntD[w], idxD, lane);
        float4 b1 = reinterpret_cast<const float4*>(b)[1 * 32 + lane];
        float4 b2 = reinterpret_cast<const float4*>(b)[2 * 32 + lane];
        float4 b3 = reinterpret_cast<const float4*>(b)[3 * 32 + lane];
        float4 v;
        v.x = fmaf(a1.x, s1, b1.x) + fmaf(a2.x, s2, b2.x) + fmaf(a3.x, s3, b3.x);
        v.y = fmaf(a1.y, s1, b1.y) + fmaf(a2.y, s2, b2.y) + fmaf(a3.y, s3, b3.y);
        v.z = fmaf(a1.z, s1, b1.z) + fmaf(a2.z, s2, b2.z) + fmaf(a3.z, s3, b3.z);
        v.w = fmaf(a1.w, s1, b1.w) + fmaf(a2.w, s2, b2.w) + fmaf(a3.w, s3, b3.w);
        if (relu) { v.x = fmaxf(v.x, 0.f); v.y = fmaxf(v.y, 0.f); v.z = fmaxf(v.z, 0.f); v.w = fmaxf(v.w, 0.f); }
        reinterpret_cast<float4*>(out)[w * 32 + lane] = v;
    } else {
        float2 a1 = segsum2(reinterpret_cast<const float2*>(yB), offB[w], cntB[w], idxB, lane);
        float2 a2 = segsum2(reinterpret_cast<const float2*>(yC), offC[w], cntC[w], idxC, lane);
        float2 a3 = segsum2(reinterpret_cast<const float2*>(yD), offD[w], cntD[w], idxD, lane);
        float2 b1 = reinterpret_cast<const float2*>(b)[1 * 32 + lane];
        float2 b2 = reinterpret_cast<const float2*>(b)[2 * 32 + lane];
        float2 b3 = reinterpret_cast<const float2*>(b)[3 * 32 + lane];
        float2 v;
        v.x = fmaf(a1.x, s1, b1.x) + fmaf(a2.x, s2, b2.x) + fmaf(a3.x, s3, b3.x);
        v.y = fmaf(a1.y, s1, b1.y) + fmaf(a2.y, s2, b2.y) + fmaf(a3.y, s3, b3.y);
        if (relu) { v.x = fmaxf(v.x, 0.f); v.y = fmaxf(v.y, 0.f); }
        reinterpret_cast<float2*>(out)[w * 32 + lane] = v;
    }
}

// ---------------------------------------------------------------------------
// Host side
// ---------------------------------------------------------------------------
struct Scratch {
    float *rs_r_src, *rs_r_dst, *rs_s_src, *rs_s_dst;
    float *hd_a, *hd_b, *hs_a, *hs_b;
    float *y_rel, *y_relby, *y_sim, *y_simby;
    int *cntA, *offA, *curA, *idxA;
    int *cntB, *offB, *curB, *idxB;
    int *cntC, *offC, *curC, *idxC;
    int *cntD, *offD, *curD, *idxD;
    int *bsum;
};

static inline int cdiv(long long a, long long b) { return (int)((a + b - 1) / b); }

static void run_scan(const int* cnt, int* off, int* cur, int* bsum, int n) {
    int nb = cdiv(n, 1024);
    scan_blk<<<nb, 1024>>>(cnt, off, bsum, n);
    scan_top<<<1, 128>>>(bsum, nb);
    scan_add<<<nb, 1024>>>(off, bsum, n);
    copy_i<<<cdiv(n, 256), 256>>>(cur, off, n);
}

template <int NOUT>
static void run_layer(const Scratch& S,
                      const float* hd_in, const float* hs_in,
                      float* hd_out, float* hs_out,
                      const float* W, const float* b, int relu) {
    const int smem = (64 * 128 + 128 * NOUT) * 4;
    const long long ws = 128LL * NOUT;

    gemm_scaled<NOUT><<<cdiv(NDRUG, 64), 256, smem>>>(hd_in, S.rs_r_src, W + 0 * ws, S.y_rel, NDRUG);
    gemm_scaled<NOUT><<<cdiv(NSIDE, 64), 256, smem>>>(hs_in, S.rs_r_dst, W + 1 * ws, S.y_relby, NSIDE);
    gemm_scaled<NOUT><<<cdiv(NDRUG, 64), 256, smem>>>(hd_in, S.rs_s_src, W + 2 * ws, S.y_sim, NDRUG);
    gemm_scaled<NOUT><<<cdiv(NDRUG, 64), 256, smem>>>(hd_in, S.rs_s_dst, W + 3 * ws, S.y_simby, NDRUG);

    gather_side<NOUT><<<cdiv(NSIDE, 8), 256>>>(
        S.y_rel, S.offA, S.cntA, S.idxA, S.rs_r_dst, b + 0 * NOUT, hs_out, relu);
    gather_drug<NOUT><<<cdiv(NDRUG, 8), 256>>>(
        S.y_relby, S.offB, S.cntB, S.idxB, S.rs_r_src,
        S.y_sim,   S.offC, S.cntC, S.idxC, S.rs_s_dst,
        S.y_simby, S.offD, S.cntD, S.idxD, S.rs_s_src,
        b, hd_out, relu);
}

extern "C" void kernel_launch(void* const* d_in, const int* in_sizes, int n_in,
                              void* d_out, int out_size) {
    const float* embed_drug = (const float*)d_in[0];
    const float* embed_side = (const float*)d_in[1];
    const int* rsrc = (const int*)d_in[2];
    const int* rdst = (const int*)d_in[3];
    const int* ssrc = (const int*)d_in[4];
    const int* sdst = (const int*)d_in[5];
    const float* W1 = (const float*)d_in[6];
    const float* b1 = (const float*)d_in[7];
    const float* W2 = (const float*)d_in[8];
    const float* b2 = (const float*)d_in[9];
    const float* W3 = (const float*)d_in[10];
    const float* b3 = (const float*)d_in[11];
    const int Er = in_sizes[2];
    const int Es = in_sizes[4];

    cudaFuncSetAttribute(gemm_scaled<128>, cudaFuncAttributeMaxDynamicSharedMemorySize,
                         (64 * 128 + 128 * 128) * 4);
    cudaFuncSetAttribute(gemm_scaled<64>, cudaFuncAttributeMaxDynamicSharedMemorySize,
                         (64 * 128 + 128 * 64) * 4);

    Scratch S;
    cudaGetSymbolAddress((void**)&S.rs_r_src, g_rs_r_src);
    cudaGetSymbolAddress((void**)&S.rs_r_dst, g_rs_r_dst);
    cudaGetSymbolAddress((void**)&S.rs_s_src, g_rs_s_src);
    cudaGetSymbolAddress((void**)&S.rs_s_dst, g_rs_s_dst);
    cudaGetSymbolAddress((void**)&S.hd_a, g_hd_a);
    cudaGetSymbolAddress((void**)&S.hd_b, g_hd_b);
    cudaGetSymbolAddress((void**)&S.hs_a, g_hs_a);
    cudaGetSymbolAddress((void**)&S.hs_b, g_hs_b);
    cudaGetSymbolAddress((void**)&S.y_rel, g_y_rel);
    cudaGetSymbolAddress((void**)&S.y_relby, g_y_relby);
    cudaGetSymbolAddress((void**)&S.y_sim, g_y_sim);
    cudaGetSymbolAddress((void**)&S.y_simby, g_y_simby);
    cudaGetSymbolAddress((void**)&S.cntA, g_cntA);
    cudaGetSymbolAddress((void**)&S.offA, g_offA);
    cudaGetSymbolAddress((void**)&S.curA, g_curA);
    cudaGetSymbolAddress((void**)&S.idxA, g_idxA);
    cudaGetSymbolAddress((void**)&S.cntB, g_cntB);
    cudaGetSymbolAddress((void**)&S.offB, g_offB);
    cudaGetSymbolAddress((void**)&S.curB, g_curB);
    cudaGetSymbolAddress((void**)&S.idxB, g_idxB);
    cudaGetSymbolAddress((void**)&S.cntC, g_cntC);
    cudaGetSymbolAddress((void**)&S.offC, g_offC);
    cudaGetSymbolAddress((void**)&S.curC, g_curC);
    cudaGetSymbolAddress((void**)&S.idxC, g_idxC);
    cudaGetSymbolAddress((void**)&S.cntD, g_cntD);
    cudaGetSymbolAddress((void**)&S.offD, g_offD);
    cudaGetSymbolAddress((void**)&S.curD, g_curD);
    cudaGetSymbolAddress((void**)&S.idxD, g_idxD);
    cudaGetSymbolAddress((void**)&S.bsum, g_bsum);

    // --- CSR build + degrees (once; shared by all 3 layers) ---
    zero_i4<<<cdiv(NSIDE / 4, 256), 256>>>((int4*)S.cntA, NSIDE / 4);
    zero_i4<<<cdiv(NDRUG / 4, 256), 256>>>((int4*)S.cntB, NDRUG / 4);
    zero_i4<<<cdiv(NDRUG / 4, 256), 256>>>((int4*)S.cntC, NDRUG / 4);
    zero_i4<<<cdiv(NDRUG / 4, 256), 256>>>((int4*)S.cntD, NDRUG / 4);
    int Emax = Er > Es ? Er : Es;
    hist_kernel<<<cdiv(Emax, 256), 256>>>(rsrc, rdst, ssrc, sdst, Er, Es,
                                          S.cntA, S.cntB, S.cntC, S.cntD);
    rs_all<<<cdiv(NDRUG, 256), 256>>>(S.cntA, S.cntB, S.cntC, S.cntD,
                                      S.rs_r_dst, S.rs_r_src, S.rs_s_dst, S.rs_s_src);
    run_scan(S.cntA, S.offA, S.curA, S.bsum, NSIDE);
    run_scan(S.cntB, S.offB, S.curB, S.bsum, NDRUG);
    run_scan(S.cntC, S.offC, S.curC, S.bsum, NDRUG);
    run_scan(S.cntD, S.offD, S.curD, S.bsum, NDRUG);
    fill_all<<<cdiv(Emax, 256), 256>>>(rsrc, rdst, ssrc, sdst, Er, Es,
                                       S.curA, S.idxA, S.curB, S.idxB,
                                       S.curC, S.idxC, S.curD, S.idxD);

    // --- 3 layers ---
    run_layer<128>(S, embed_drug, embed_side, S.hd_a, S.hs_a, W1, b1, 1);
    run_layer<128>(S, S.hd_a, S.hs_a, S.hd_b, S.hs_b, W2, b2, 1);

    float* out = (float*)d_out;
    run_layer<64>(S, S.hd_b, S.hs_b, out, out + (long long)NDRUG * 64, W3, b3, 0);
}

// round 5
// speedup vs baseline: 1.8442x; 1.4190x over previous
#include <cuda_runtime.h>
#include <cstdint>

#define NDRUG 100000
#define NSIDE 5000
#define FDIM  128
#define EMAX  1000000

// ---------------------------------------------------------------------------
// Static device scratch
// ---------------------------------------------------------------------------
__device__ __align__(16) float g_rs_r_src[NDRUG];
__device__ __align__(16) float g_rs_r_dst[NSIDE];
__device__ __align__(16) float g_rs_s_src[NDRUG];
__device__ __align__(16) float g_rs_s_dst[NDRUG];

__device__ __align__(16) float g_hd_a[NDRUG * FDIM];
__device__ __align__(16) float g_hd_b[NDRUG * FDIM];
__device__ __align__(16) float g_hs_a[NSIDE * FDIM];
__device__ __align__(16) float g_hs_b[NSIDE * FDIM];

__device__ __align__(16) float g_y_rel[NDRUG * FDIM];
__device__ __align__(16) float g_y_relby[NSIDE * FDIM];
__device__ __align__(16) float g_y_sim[NDRUG * FDIM];
__device__ __align__(16) float g_y_simby[NDRUG * FDIM];

// CSR: A by relate_dst(side)<-relate_src ; B by relate_src(drug)<-relate_dst ;
//      C by sim_dst(drug)<-sim_src ; D by sim_src(drug)<-sim_dst
__device__ __align__(16) int g_cntA[NSIDE], g_offA[NSIDE], g_curA[NSIDE];
__device__ __align__(16) int g_cntB[NDRUG], g_offB[NDRUG], g_curB[NDRUG];
__device__ __align__(16) int g_cntC[NDRUG], g_offC[NDRUG], g_curC[NDRUG];
__device__ __align__(16) int g_cntD[NDRUG], g_offD[NDRUG], g_curD[NDRUG];
__device__ __align__(16) int g_idxA[EMAX], g_idxB[EMAX], g_idxC[EMAX], g_idxD[EMAX];

// ---------------------------------------------------------------------------
// Utility kernels
// ---------------------------------------------------------------------------
__global__ void zero_cnts(int4* __restrict__ a, int4* __restrict__ b,
                          int4* __restrict__ c, int4* __restrict__ d) {
    int i = blockIdx.x * blockDim.x + threadIdx.x;
    int4 z = make_int4(0, 0, 0, 0);
    if (i < NSIDE / 4) a[i] = z;
    if (i < NDRUG / 4) { b[i] = z; c[i] = z; d[i] = z; }
}

__global__ void hist_kernel(const int* __restrict__ rsrc, const int* __restrict__ rdst,
                            const int* __restrict__ ssrc, const int* __restrict__ sdst,
                            int Er, int Es,
                            int* __restrict__ cA, int* __restrict__ cB,
                            int* __restrict__ cC, int* __restrict__ cD) {
    int e = blockIdx.x * blockDim.x + threadIdx.x;
    if (e < Er) {
        atomicAdd(&cA[rdst[e]], 1);
        atomicAdd(&cB[rsrc[e]], 1);
    }
    if (e < Es) {
        atomicAdd(&cC[sdst[e]], 1);
        atomicAdd(&cD[ssrc[e]], 1);
    }
}

// 4 blocks; each block scans one cnt array into off + cur and emits
// rs = rsqrt(max(cnt,1)).
__global__ void scan4(const int* __restrict__ cA, const int* __restrict__ cB,
                      const int* __restrict__ cC, const int* __restrict__ cD,
                      int* __restrict__ offA, int* __restrict__ curA, float* __restrict__ rsA,
                      int* __restrict__ offB, int* __restrict__ curB, float* __restrict__ rsB,
                      int* __restrict__ offC, int* __restrict__ curC, float* __restrict__ rsC,
                      int* __restrict__ offD, int* __restrict__ curD, float* __restrict__ rsD) {
    __shared__ int sm[1024];
    int b = blockIdx.x, tid = threadIdx.x;
    const int* cnt; int* off; int* cur; float* rs; int n;
    if (b == 0)      { cnt = cA; off = offA; cur = curA; rs = rsA; n = NSIDE; }
    else if (b == 1) { cnt = cB; off = offB; cur = curB; rs = rsB; n = NDRUG; }
    else if (b == 2) { cnt = cC; off = offC; cur = curC; rs = rsC; n = NDRUG; }
    else             { cnt = cD; off = offD; cur = curD; rs = rsD; n = NDRUG; }

    int chunk = (n + 1023) >> 10;
    int s0 = tid * chunk;
    int s1 = min(s0 + chunk, n);
    int s = 0;
    for (int i = s0; i < s1; ++i) s += cnt[i];
    sm[tid] = s;
    __syncthreads();
    for (int d = 1; d < 1024; d <<= 1) {
        int x = (tid >= d) ? sm[tid - d] : 0;
        __syncthreads();
        sm[tid] += x;
        __syncthreads();
    }
    int run = sm[tid] - s;  // exclusive prefix
    for (int i = s0; i < s1; ++i) {
        int c = cnt[i];
        off[i] = run;
        cur[i] = run;
        rs[i] = rsqrtf((float)(c > 0 ? c : 1));
        run += c;
    }
}

__global__ void fill_all(const int* __restrict__ rsrc, const int* __restrict__ rdst,
                         const int* __restrict__ ssrc, const int* __restrict__ sdst,
                         int Er, int Es,
                         int* __restrict__ curA, int* __restrict__ idxA,
                         int* __restrict__ curB, int* __restrict__ idxB,
                         int* __restrict__ curC, int* __restrict__ idxC,
                         int* __restrict__ curD, int* __restrict__ idxD) {
    int e = blockIdx.x * blockDim.x + threadIdx.x;
    if (e < Er) {
        int s = rsrc[e], d = rdst[e];
        idxA[atomicAdd(&curA[d], 1)] = s;
        idxB[atomicAdd(&curB[s], 1)] = d;
    }
    if (e < Es) {
        int s = ssrc[e], d = sdst[e];
        idxC[atomicAdd(&curC[d], 1)] = s;
        idxD[atomicAdd(&curD[s], 1)] = d;
    }
}

// ---------------------------------------------------------------------------
// tf32 tensor-core multi-relation GEMM.
// Computes, for r in [0, NREL):  Yr = diag(rsr) * (X @ Wr)
// (scale applied at epilogue; X tile staged ONCE, reused for all relations).
// Block: 256 thr (8 warps), tile 64 rows x NOUT cols, full K=128 in smem.
// Warp grid 2(M) x 4(N); mma.sync m16n8k8 tf32.
// ---------------------------------------------------------------------------
__device__ __forceinline__ uint32_t f2tf(float f) {
    uint32_t r;
    asm("cvt.rna.tf32.f32 %0, %1;" : "=r"(r) : "f"(f));
    return r;
}
__device__ __forceinline__ void mma_tf32(float* d, const uint32_t* a, uint32_t b0, uint32_t b1) {
    asm("mma.sync.aligned.m16n8k8.row.col.f32.tf32.tf32.f32 "
        "{%0,%1,%2,%3}, {%4,%5,%6,%7}, {%8,%9}, {%0,%1,%2,%3};"
        : "+f"(d[0]), "+f"(d[1]), "+f"(d[2]), "+f"(d[3])
        : "r"(a[0]), "r"(a[1]), "r"(a[2]), "r"(a[3]), "r"(b0), "r"(b1));
}

template <int NOUT, int NREL>
__global__ __launch_bounds__(256) void gemm_tf32_multi(
    const float* __restrict__ X, int n,
    const float* __restrict__ W0, const float* __restrict__ W1, const float* __restrict__ W2,
    const float* __restrict__ rs0, const float* __restrict__ rs1, const float* __restrict__ rs2,
    float* __restrict__ Y0, float* __restrict__ Y1, float* __restrict__ Y2) {
    constexpr int XP = 132;        // Xs pitch (words); 132 % 32 == 4 -> A reads conflict-free
    constexpr int WP = NOUT + 8;   // Ws pitch; % 32 == 8 -> B reads conflict-free
    constexpr int WN = NOUT / 4;   // cols per warp
    constexpr int NT = WN / 8;     // n8-tiles per warp

    extern __shared__ uint32_t smu[];
    uint32_t* Xs = smu;            // 64 * XP
    uint32_t* Ws = smu + 64 * XP;  // 128 * WP

    const int tid = threadIdx.x;
    const int row0 = blockIdx.x * 64;

    // Fill X tile once (unscaled, tf32)
    for (int i = tid; i < 64 * 32; i += 256) {
        int r = i >> 5, c4 = i & 31;
        int row = row0 + r;
        float4 v = make_float4(0.f, 0.f, 0.f, 0.f);
        if (row < n) v = reinterpret_cast<const float4*>(X)[row * 32 + c4];
        uint4 u = make_uint4(f2tf(v.x), f2tf(v.y), f2tf(v.z), f2tf(v.w));
        *reinterpret_cast<uint4*>(&Xs[r * XP + c4 * 4]) = u;
    }

    const int lane = tid & 31, wid = tid >> 5;
    const int g = lane >> 2, t = lane & 3;
    const int wm = wid & 1, wn = wid >> 1;
    const int nbase = wn * WN;
    const uint32_t* xbase = Xs + (wm * 32) * XP;

    #pragma unroll
    for (int rel = 0; rel < NREL; ++rel) {
        const float* W  = (rel == 0) ? W0  : (rel == 1) ? W1  : W2;
        const float* rs = (rel == 0) ? rs0 : (rel == 1) ? rs1 : rs2;
        float* Y        = (rel == 0) ? Y0  : (rel == 1) ? Y1  : Y2;

        __syncthreads();   // protect Ws (and Xs on first pass) before (re)fill
        for (int i = tid; i < 128 * (NOUT / 4); i += 256) {
            int k = i / (NOUT / 4), c4 = i % (NOUT / 4);
            float4 v = reinterpret_cast<const float4*>(W)[i];
            uint4 u = make_uint4(f2tf(v.x), f2tf(v.y), f2tf(v.z), f2tf(v.w));
            *reinterpret_cast<uint4*>(&Ws[k * WP + c4 * 4]) = u;
        }
        __syncthreads();

        float acc[2][NT][4];
        #pragma unroll
        for (int mi = 0; mi < 2; ++mi)
            #pragma unroll
            for (int ni = 0; ni < NT; ++ni)
                #pragma unroll
                for (int j = 0; j < 4; ++j) acc[mi][ni][j] = 0.f;

        #pragma unroll
        for (int ks = 0; ks < 16; ++ks) {
            const int k0 = ks * 8;
            uint32_t a[2][4];
            #pragma unroll
            for (int mi = 0; mi < 2; ++mi) {
                const uint32_t* xb = xbase + mi * 16 * XP + k0;
                a[mi][0] = xb[g * XP + t];
                a[mi][1] = xb[(g + 8) * XP + t];
                a[mi][2] = xb[g * XP + t + 4];
                a[mi][3] = xb[(g + 8) * XP + t + 4];
            }
            #pragma unroll
            for (int ni = 0; ni < NT; ++ni) {
                uint32_t b0 = Ws[(k0 + t) * WP + nbase + ni * 8 + g];
                uint32_t b1 = Ws[(k0 + t + 4) * WP + nbase + ni * 8 + g];
                #pragma unroll
                for (int mi = 0; mi < 2; ++mi) mma_tf32(acc[mi][ni], a[mi], b0, b1);
            }
        }

        // Epilogue: apply per-row rs scale, write Y
        #pragma unroll
        for (int mi = 0; mi < 2; ++mi) {
            int r0 = row0 + wm * 32 + mi * 16 + g;
            float sa = (r0 < n) ? rs[r0] : 0.f;
            float sb = (r0 + 8 < n) ? rs[r0 + 8] : 0.f;
            #pragma unroll
            for (int ni = 0; ni < NT; ++ni) {
                int col = nbase + ni * 8 + 2 * t;
                if (r0 < n)
                    *reinterpret_cast<float2*>(&Y[(long long)r0 * NOUT + col]) =
                        make_float2(acc[mi][ni][0] * sa, acc[mi][ni][1] * sa);
                if (r0 + 8 < n)
                    *reinterpret_cast<float2*>(&Y[(long long)(r0 + 8) * NOUT + col]) =
                        make_float2(acc[mi][ni][2] * sb, acc[mi][ni][3] * sb);
            }
        }
    }
}

// ---------------------------------------------------------------------------
// Merged CSR gather: first NSIDE warps handle side rows, then NDRUG warps
// handle drug rows (3-relation sum). One warp per dst row.
// ---------------------------------------------------------------------------
__device__ __forceinline__ float4 segsum4(const float4* __restrict__ Y, int beg, int m,
                                          const int* __restrict__ idx, int lane) {
    float4 acc = make_float4(0.f, 0.f, 0.f, 0.f);
    for (int e0 = 0; e0 < m; e0 += 32) {
        int myi = (e0 + lane < m) ? idx[beg + e0 + lane] : 0;
        int lim = min(32, m - e0);
        #pragma unroll 4
        for (int j = 0; j < lim; ++j) {
            int s = __shfl_sync(0xffffffffu, myi, j);
            float4 v = Y[s * 32 + lane];
            acc.x += v.x; acc.y += v.y; acc.z += v.z; acc.w += v.w;
        }
    }
    return acc;
}
__device__ __forceinline__ float2 segsum2(const float2* __restrict__ Y, int beg, int m,
                                          const int* __restrict__ idx, int lane) {
    float2 acc = make_float2(0.f, 0.f);
    for (int e0 = 0; e0 < m; e0 += 32) {
        int myi = (e0 + lane < m) ? idx[beg + e0 + lane] : 0;
        int lim = min(32, m - e0);
        #pragma unroll 4
        for (int j = 0; j < lim; ++j) {
            int s = __shfl_sync(0xffffffffu, myi, j);
            float2 v = Y[s * 32 + lane];
            acc.x += v.x; acc.y += v.y;
        }
    }
    return acc;
}

template <int NOUT>
__global__ __launch_bounds__(256) void gather_all(
    const float* __restrict__ yA, const int* __restrict__ offA, const int* __restrict__ cntA,
    const int* __restrict__ idxA, const float* __restrict__ rsA,
    const float* __restrict__ yB, const int* __restrict__ offB, const int* __restrict__ cntB,
    const int* __restrict__ idxB, const float* __restrict__ rsB,
    const float* __restrict__ yC, const int* __restrict__ offC, const int* __restrict__ cntC,
    const int* __restrict__ idxC, const float* __restrict__ rsC,
    const float* __restrict__ yD, const int* __restrict__ offD, const int* __restrict__ cntD,
    const int* __restrict__ idxD, const float* __restrict__ rsD,
    const float* __restrict__ b, float* __restrict__ out_side, float* __restrict__ out_drug,
    int relu) {
    int w = (blockIdx.x * blockDim.x + threadIdx.x) >> 5;
    int lane = threadIdx.x & 31;

    if (w < NSIDE) {
        float s = rsA[w];
        if constexpr (NOUT == 128) {
            float4 a = segsum4(reinterpret_cast<const float4*>(yA), offA[w], cntA[w], idxA, lane);
            float4 bb = reinterpret_cast<const float4*>(b)[lane];
            float4 v = make_float4(fmaf(a.x, s, bb.x), fmaf(a.y, s, bb.y),
                                   fmaf(a.z, s, bb.z), fmaf(a.w, s, bb.w));
            if (relu) { v.x = fmaxf(v.x, 0.f); v.y = fmaxf(v.y, 0.f); v.z = fmaxf(v.z, 0.f); v.w = fmaxf(v.w, 0.f); }
            reinterpret_cast<float4*>(out_side)[w * 32 + lane] = v;
        } else {
            float2 a = segsum2(reinterpret_cast<const float2*>(yA), offA[w], cntA[w], idxA, lane);
            float2 bb = reinterpret_cast<const float2*>(b)[lane];
            float2 v = make_float2(fmaf(a.x, s, bb.x), fmaf(a.y, s, bb.y));
            if (relu) { v.x = fmaxf(v.x, 0.f); v.y = fmaxf(v.y, 0.f); }
            reinterpret_cast<float2*>(out_side)[w * 32 + lane] = v;
        }
        return;
    }
    int d = w - NSIDE;
    if (d >= NDRUG) return;
    float s1 = rsB[d], s2 = rsC[d], s3 = rsD[d];
    if constexpr (NOUT == 128) {
        float4 a1 = segsum4(reinterpret_cast<const float4*>(yB), offB[d], cntB[d], idxB, lane);
        float4 a2 = segsum4(reinterpret_cast<const float4*>(yC), offC[d], cntC[d], idxC, lane);
        float4 a3 = segsum4(reinterpret_cast<const float4*>(yD), offD[d], cntD[d], idxD, lane);
        float4 b1 = reinterpret_cast<const float4*>(b)[1 * 32 + lane];
        float4 b2 = reinterpret_cast<const float4*>(b)[2 * 32 + lane];
        float4 b3 = reinterpret_cast<const float4*>(b)[3 * 32 + lane];
        float4 v;
        v.x = fmaf(a1.x, s1, b1.x) + fmaf(a2.x, s2, b2.x) + fmaf(a3.x, s3, b3.x);
        v.y = fmaf(a1.y, s1, b1.y) + fmaf(a2.y, s2, b2.y) + fmaf(a3.y, s3, b3.y);
        v.z = fmaf(a1.z, s1, b1.z) + fmaf(a2.z, s2, b2.z) + fmaf(a3.z, s3, b3.z);
        v.w = fmaf(a1.w, s1, b1.w) + fmaf(a2.w, s2, b2.w) + fmaf(a3.w, s3, b3.w);
        if (relu) { v.x = fmaxf(v.x, 0.f); v.y = fmaxf(v.y, 0.f); v.z = fmaxf(v.z, 0.f); v.w = fmaxf(v.w, 0.f); }
        reinterpret_cast<float4*>(out_drug)[d * 32 + lane] = v;
    } else {
        float2 a1 = segsum2(reinterpret_cast<const float2*>(yB), offB[d], cntB[d], idxB, lane);
        float2 a2 = segsum2(reinterpret_cast<const float2*>(yC), offC[d], cntC[d], idxC, lane);
        float2 a3 = segsum2(reinterpret_cast<const float2*>(yD), offD[d], cntD[d], idxD, lane);
        float2 b1 = reinterpret_cast<const float2*>(b)[1 * 32 + lane];
        float2 b2 = reinterpret_cast<const float2*>(b)[2 * 32 + lane];
        float2 b3 = reinterpret_cast<const float2*>(b)[3 * 32 + lane];
        float2 v;
        v.x = fmaf(a1.x, s1, b1.x) + fmaf(a2.x, s2, b2.x) + fmaf(a3.x, s3, b3.x);
        v.y = fmaf(a1.y, s1, b1.y) + fmaf(a2.y, s2, b2.y) + fmaf(a3.y, s3, b3.y);
        if (relu) { v.x = fmaxf(v.x, 0.f); v.y = fmaxf(v.y, 0.f); }
        reinterpret_cast<float2*>(out_drug)[d * 32 + lane] = v;
    }
}

// ---------------------------------------------------------------------------
// Host side
// ---------------------------------------------------------------------------
struct Scratch {
    float *rs_r_src, *rs_r_dst, *rs_s_src, *rs_s_dst;
    float *hd_a, *hd_b, *hs_a, *hs_b;
    float *y_rel, *y_relby, *y_sim, *y_simby;
    int *cntA, *offA, *curA, *idxA;
    int *cntB, *offB, *curB, *idxB;
    int *cntC, *offC, *curC, *idxC;
    int *cntD, *offD, *curD, *idxD;
};

static inline int cdiv(long long a, long long b) { return (int)((a + b - 1) / b); }

template <int NOUT>
static void run_layer(const Scratch& S,
                      const float* hd_in, const float* hs_in,
                      float* hd_out, float* hs_out,
                      const float* W, const float* b, int relu) {
    constexpr int XP = 132, WP = NOUT + 8;
    const int smem = (64 * XP + 128 * WP) * 4;
    const long long ws = 128LL * NOUT;

    // Drug projections: relations 0 (relate), 2 (sim), 3 (sim-by), sharing X
    gemm_tf32_multi<NOUT, 3><<<cdiv(NDRUG, 64), 256, smem>>>(
        hd_in, NDRUG,
        W + 0 * ws, W + 2 * ws, W + 3 * ws,
        S.rs_r_src, S.rs_s_src, S.rs_s_dst,
        S.y_rel, S.y_sim, S.y_simby);
    // Side projection: relation 1 (relate-by)
    gemm_tf32_multi<NOUT, 1><<<cdiv(NSIDE, 64), 256, smem>>>(
        hs_in, NSIDE,
        W + 1 * ws, W + 1 * ws, W + 1 * ws,
        S.rs_r_dst, S.rs_r_dst, S.rs_r_dst,
        S.y_relby, S.y_relby, S.y_relby);

    gather_all<NOUT><<<cdiv((NDRUG + NSIDE) * 32, 256), 256>>>(
        S.y_rel, S.offA, S.cntA, S.idxA, S.rs_r_dst,
        S.y_relby, S.offB, S.cntB, S.idxB, S.rs_r_src,
        S.y_sim,   S.offC, S.cntC, S.idxC, S.rs_s_dst,
        S.y_simby, S.offD, S.cntD, S.idxD, S.rs_s_src,
        b, hs_out, hd_out, relu);
}

extern "C" void kernel_launch(void* const* d_in, const int* in_sizes, int n_in,
                              void* d_out, int out_size) {
    const float* embed_drug = (const float*)d_in[0];
    const float* embed_side = (const float*)d_in[1];
    const int* rsrc = (const int*)d_in[2];
    const int* rdst = (const int*)d_in[3];
    const int* ssrc = (const int*)d_in[4];
    const int* sdst = (const int*)d_in[5];
    const float* W1 = (const float*)d_in[6];
    const float* b1 = (const float*)d_in[7];
    const float* W2 = (const float*)d_in[8];
    const float* b2 = (const float*)d_in[9];
    const float* W3 = (const float*)d_in[10];
    const float* b3 = (const float*)d_in[11];
    const int Er = in_sizes[2];
    const int Es = in_sizes[4];

    const int sm128 = (64 * 132 + 128 * 136) * 4;
    const int sm64  = (64 * 132 + 128 * 72) * 4;
    cudaFuncSetAttribute(gemm_tf32_multi<128, 3>, cudaFuncAttributeMaxDynamicSharedMemorySize, sm128);
    cudaFuncSetAttribute(gemm_tf32_multi<128, 1>, cudaFuncAttributeMaxDynamicSharedMemorySize, sm128);
    cudaFuncSetAttribute(gemm_tf32_multi<64, 3>, cudaFuncAttributeMaxDynamicSharedMemorySize, sm64);
    cudaFuncSetAttribute(gemm_tf32_multi<64, 1>, cudaFuncAttributeMaxDynamicSharedMemorySize, sm64);

    Scratch S;
    cudaGetSymbolAddress((void**)&S.rs_r_src, g_rs_r_src);
    cudaGetSymbolAddress((void**)&S.rs_r_dst, g_rs_r_dst);
    cudaGetSymbolAddress((void**)&S.rs_s_src, g_rs_s_src);
    cudaGetSymbolAddress((void**)&S.rs_s_dst, g_rs_s_dst);
    cudaGetSymbolAddress((void**)&S.hd_a, g_hd_a);
    cudaGetSymbolAddress((void**)&S.hd_b, g_hd_b);
    cudaGetSymbolAddress((void**)&S.hs_a, g_hs_a);
    cudaGetSymbolAddress((void**)&S.hs_b, g_hs_b);
    cudaGetSymbolAddress((void**)&S.y_rel, g_y_rel);
    cudaGetSymbolAddress((void**)&S.y_relby, g_y_relby);
    cudaGetSymbolAddress((void**)&S.y_sim, g_y_sim);
    cudaGetSymbolAddress((void**)&S.y_simby, g_y_simby);
    cudaGetSymbolAddress((void**)&S.cntA, g_cntA);
    cudaGetSymbolAddress((void**)&S.offA, g_offA);
    cudaGetSymbolAddress((void**)&S.curA, g_curA);
    cudaGetSymbolAddress((void**)&S.idxA, g_idxA);
    cudaGetSymbolAddress((void**)&S.cntB, g_cntB);
    cudaGetSymbolAddress((void**)&S.offB, g_offB);
    cudaGetSymbolAddress((void**)&S.curB, g_curB);
    cudaGetSymbolAddress((void**)&S.idxB, g_idxB);
    cudaGetSymbolAddress((void**)&S.cntC, g_cntC);
    cudaGetSymbolAddress((void**)&S.offC, g_offC);
    cudaGetSymbolAddress((void**)&S.curC, g_curC);
    cudaGetSymbolAddress((void**)&S.idxC, g_idxC);
    cudaGetSymbolAddress((void**)&S.cntD, g_cntD);
    cudaGetSymbolAddress((void**)&S.offD, g_offD);
    cudaGetSymbolAddress((void**)&S.curD, g_curD);
    cudaGetSymbolAddress((void**)&S.idxD, g_idxD);

    // --- CSR build + degrees (4 launches) ---
    zero_cnts<<<cdiv(NDRUG / 4, 256), 256>>>((int4*)S.cntA, (int4*)S.cntB,
                                             (int4*)S.cntC, (int4*)S.cntD);
    int Emax = Er > Es ? Er : Es;
    hist_kernel<<<cdiv(Emax, 256), 256>>>(rsrc, rdst, ssrc, sdst, Er, Es,
                                          S.cntA, S.cntB, S.cntC, S.cntD);
    scan4<<<4, 1024>>>(S.cntA, S.cntB, S.cntC, S.cntD,
                       S.offA, S.curA, S.rs_r_dst,
                       S.offB, S.curB, S.rs_r_src,
                       S.offC, S.curC, S.rs_s_dst,
                       S.offD, S.curD, S.rs_s_src);
    fill_all<<<cdiv(Emax, 256), 256>>>(rsrc, rdst, ssrc, sdst, Er, Es,
                                       S.curA, S.idxA, S.curB, S.idxB,
                                       S.curC, S.idxC, S.curD, S.idxD);

    // --- 3 layers ---
    run_layer<128>(S, embed_drug, embed_side, S.hd_a, S.hs_a, W1, b1, 1);
    run_layer<128>(S, S.hd_a, S.hs_a, S.hd_b, S.hs_b, W2, b2, 1);

    float* out = (float*)d_out;
    run_layer<64>(S, S.hd_b, S.hs_b, out, out + (long long)NDRUG * 64, W3, b3, 0);
}